// round 3
// baseline (speedup 1.0000x reference)
#include <cuda_runtime.h>
#include <math.h>

// Problem shapes (fixed by the reference)
#define NB 8192          // batch
#define SS 10            // senses
#define HH 1024          // hidden
#define THREADS 256
#define MIN_BLOCKS_SM 5  // 48-51 regs -> 5 blocks/SM resident
#define NBLOCKS (148 * MIN_BLOCKS_SM)   // 740: exactly one full resident wave
#define ALPHA_ROWS 16200 // 2700*6
#define ALPHA_CHUNKS 64
#define ALPHA_CHUNK 254  // 64*254 = 16256 >= 16200
#define NTICKETS (NB + ALPHA_CHUNKS)

// Scratch (device globals: no allocation allowed anywhere)
__device__ float g_margin_part[NB];
__device__ float g_alpha_part[ALPHA_CHUNKS];
__device__ unsigned int g_ticket;  // zero-init; self-resetting
__device__ unsigned int g_done;    // zero-init; self-resetting

__global__ __launch_bounds__(THREADS, MIN_BLOCKS_SM)
void marginal_loss_fused(const float* __restrict__ sentence,
                         const float* __restrict__ gloss,
                         const float* __restrict__ alpha,
                         const int*   __restrict__ mask,
                         const int*   __restrict__ sids,
                         float* __restrict__ out, int out_size)
{
    const int lane = threadIdx.x & 31;

    // ---- dynamic ticket loop: perfect balance across SMs ----
    for (;;) {
        unsigned int t;
        if (lane == 0) t = atomicAdd(&g_ticket, 1u);
        t = __shfl_sync(0xffffffffu, t, 0);
        if (t >= NTICKETS) break;

        if (t < NB) {
            // ---- margin row t: one warp computes 10 distances in one pass ----
            const int b = (int)t;
            const float4* __restrict__ srow =
                reinterpret_cast<const float4*>(sentence + (size_t)b * HH);
            float4 sv[8];
            #pragma unroll
            for (int j = 0; j < 8; ++j) sv[j] = srow[lane + j * 32];

            float acc[SS];
            #pragma unroll
            for (int s = 0; s < SS; ++s) {
                const float4* __restrict__ grow = reinterpret_cast<const float4*>(
                    gloss + ((size_t)b * SS + s) * HH);
                // 4 independent accumulators: FMA chain 32 -> 8 deep
                float a0 = 0.0f, a1 = 0.0f, a2 = 0.0f, a3 = 0.0f;
                #pragma unroll
                for (int j = 0; j < 8; ++j) {
                    float4 g = grow[lane + j * 32];
                    float d0 = sv[j].x - g.x + 1e-6f;
                    float d1 = sv[j].y - g.y + 1e-6f;
                    float d2 = sv[j].z - g.z + 1e-6f;
                    float d3 = sv[j].w - g.w + 1e-6f;
                    a0 = fmaf(d0, d0, a0);
                    a1 = fmaf(d1, d1, a1);
                    a2 = fmaf(d2, d2, a2);
                    a3 = fmaf(d3, d3, a3);
                }
                acc[s] = (a0 + a1) + (a2 + a3);
            }

            #pragma unroll
            for (int s = 0; s < SS; ++s) {
                float v = acc[s];
                #pragma unroll
                for (int off = 16; off > 0; off >>= 1)
                    v += __shfl_xor_sync(0xffffffffu, v, off);
                acc[s] = v;
            }

            if (lane == 0) {
                const int sid = sids[b];
                float pos  = 0.0f;
                float minv = 1e30f;   // first strict-< win == argmin first-index tie rule
                float neg  = 0.0f;
                #pragma unroll
                for (int s = 0; s < SS; ++s) {
                    float ds = sqrtf(acc[s]);
                    if (s == sid) pos = ds;
                    bool valid = (mask[b * SS + s] != 0) && (s != sid);
                    float m = valid ? ds : 10.0f;          // SENTINEL
                    if (m < minv) { minv = m; neg = ds; }  // carry REAL distance at argmin
                }
                g_margin_part[b] = fmaxf(pos - neg + 0.5f, 0.0f);
            }
        } else {
            // ---- alpha chunk ----
            const int c     = (int)(t - NB);
            const int start = c * ALPHA_CHUNK;
            const int end   = min(start + ALPHA_CHUNK, ALPHA_ROWS);
            float part = 0.0f;
            for (int r = start + lane; r < end; r += 32) {
                const float* __restrict__ row = alpha + (size_t)r * 10;
                float s0 = 0.0f, mx = -1e30f;
                #pragma unroll
                for (int k = 0; k < 10; ++k) {
                    float v = row[k];
                    s0 += v;
                    mx = fmaxf(mx, v);
                }
                // row_sum==0 -> tmp=ones -> max=1 -> |1-1| = 0
                part += (s0 == 0.0f) ? 0.0f : fabsf(mx - 1.0f);
            }
            #pragma unroll
            for (int off = 16; off > 0; off >>= 1)
                part += __shfl_xor_sync(0xffffffffu, part, off);
            if (lane == 0) g_alpha_part[c] = part;
        }
    }

    // ---- completion-counter fused finalize (last block only) ----
    __shared__ bool s_last;
    __syncthreads();
    if (threadIdx.x == 0) {
        __threadfence();
        unsigned int d = atomicAdd(&g_done, 1u);
        s_last = (d == (unsigned int)(gridDim.x - 1));
    }
    __syncthreads();
    if (!s_last) return;

    __shared__ float sh[THREADS];

    // margin sum, fixed order -> bit-deterministic
    float m = 0.0f;
    for (int i = threadIdx.x; i < NB; i += THREADS) m += g_margin_part[i];
    sh[threadIdx.x] = m;
    __syncthreads();
    #pragma unroll
    for (int off = THREADS / 2; off > 0; off >>= 1) {
        if (threadIdx.x < off) sh[threadIdx.x] += sh[threadIdx.x + off];
        __syncthreads();
    }
    float margin = sh[0];
    __syncthreads();

    // alpha sum
    float a = (threadIdx.x < ALPHA_CHUNKS) ? g_alpha_part[threadIdx.x] : 0.0f;
    sh[threadIdx.x] = a;
    __syncthreads();
    #pragma unroll
    for (int off = THREADS / 2; off > 0; off >>= 1) {
        if (threadIdx.x < off) sh[threadIdx.x] += sh[threadIdx.x + off];
        __syncthreads();
    }
    float alpha_term = sh[0];

    if (threadIdx.x == 0) {
        float loss = margin * 0.875f + alpha_term * 0.125f;
        out[0] = loss;
        if (out_size > 1) out[1] = margin;
        if (out_size > 2) out[2] = alpha_term;
        // self-reset for next graph replay (stream order guarantees visibility)
        g_ticket = 0u;
        g_done   = 0u;
    }
}

extern "C" void kernel_launch(void* const* d_in, const int* in_sizes, int n_in,
                              void* d_out, int out_size)
{
    // Identify inputs robustly by element count (all distinct):
    //   sentence  8192*1024    = 8388608  (f32)
    //   all_gloss 8192*10*1024 = 83886080 (f32)
    //   alpha     2700*6*10    = 162000   (f32)
    //   sense_mask 8192*10     = 81920    (i32)
    //   sense_ids 8192         = 8192     (i32)
    const float* sentence = nullptr;
    const float* gloss    = nullptr;
    const float* alpha    = nullptr;
    const int*   mask     = nullptr;
    const int*   sids     = nullptr;
    for (int i = 0; i < n_in; ++i) {
        switch (in_sizes[i]) {
            case 8388608:  sentence = (const float*)d_in[i]; break;
            case 83886080: gloss    = (const float*)d_in[i]; break;
            case 162000:   alpha    = (const float*)d_in[i]; break;
            case 81920:    mask     = (const int*)  d_in[i]; break;
            case 8192:     sids     = (const int*)  d_in[i]; break;
            default: break;
        }
    }

    marginal_loss_fused<<<NBLOCKS, THREADS>>>(sentence, gloss, alpha, mask, sids,
                                              (float*)d_out, out_size);
}

// round 4
// speedup vs baseline: 1.1832x; 1.1832x over previous
#include <cuda_runtime.h>
#include <math.h>

// Problem shapes (fixed by the reference)
#define NB 8192          // batch
#define SS 10            // senses
#define HH 1024          // hidden
#define THREADS 256      // exactly HH/4 -> one float4 of the row per thread
#define NBLOCKS (148 * 4)
#define ALPHA_ROWS 16200 // 2700*6
#define ALPHA_CHUNKS 64
#define ALPHA_CHUNK 254  // 64*254 = 16256 >= 16200
#define NTICKETS (NB + ALPHA_CHUNKS)

// Scratch (device globals: no allocation allowed anywhere)
__device__ float g_margin_part[NB];
__device__ float g_alpha_part[ALPHA_CHUNKS];
__device__ unsigned int g_ticket;  // zero-init; self-resetting
__device__ unsigned int g_done;    // zero-init; self-resetting

__global__ __launch_bounds__(THREADS, 4)
void marginal_loss_fused(const float* __restrict__ sentence,
                         const float* __restrict__ gloss,
                         const float* __restrict__ alpha,
                         const int*   __restrict__ mask,
                         const int*   __restrict__ sids,
                         float* __restrict__ out, int out_size)
{
    const int tid  = threadIdx.x;
    const int lane = tid & 31;
    const int wid  = tid >> 5;

    __shared__ unsigned int s_t;
    __shared__ float sh_red[SS][8];   // per-warp partials per sense
    __shared__ int   sh_mask[SS];
    __shared__ int   sh_sid;
    __shared__ float sh_blk[THREADS]; // alpha block reduce

    // ---- dynamic block-ticket loop ----
    for (;;) {
        if (tid == 0) s_t = atomicAdd(&g_ticket, 1u);
        __syncthreads();
        const unsigned int t = s_t;
        __syncthreads();              // s_t consumed before next overwrite
        if (t >= NTICKETS) break;

        if (t < NB) {
            const int b = (int)t;

            // prefetch mask/sid (overlaps with gloss streaming)
            if (tid < SS) sh_mask[tid] = mask[b * SS + tid];
            if (tid == SS) sh_sid = sids[b];

            // sentence slice: ONE float4 per thread covers the whole row
            const float4 sv =
                reinterpret_cast<const float4*>(sentence + (size_t)b * HH)[tid];

            // 10 senses, one independent float4 load each -> MLP up to 10
            const float4* __restrict__ gbase =
                reinterpret_cast<const float4*>(gloss + (size_t)b * SS * HH);
            float acc[SS];
            #pragma unroll
            for (int s = 0; s < SS; ++s) {
                float4 g = gbase[s * THREADS + tid];
                float d0 = sv.x - g.x + 1e-6f;
                float d1 = sv.y - g.y + 1e-6f;
                float d2 = sv.z - g.z + 1e-6f;
                float d3 = sv.w - g.w + 1e-6f;
                acc[s] = fmaf(d0, d0, fmaf(d1, d1, fmaf(d2, d2, d3 * d3)));
            }

            // block reduction: warp shfl then cross-warp via shared
            #pragma unroll
            for (int s = 0; s < SS; ++s) {
                float v = acc[s];
                #pragma unroll
                for (int off = 16; off > 0; off >>= 1)
                    v += __shfl_xor_sync(0xffffffffu, v, off);
                if (lane == 0) sh_red[s][wid] = v;
            }
            __syncthreads();

            if (wid == 0) {
                // lane s (<10) owns sense s: fixed-order 8-way sum (deterministic)
                float tot = 0.0f;
                if (lane < SS) {
                    #pragma unroll
                    for (int w = 0; w < 8; ++w) tot += sh_red[lane][w];
                }
                // gather all 10 sums into lane 0 via shfl
                if (lane == 0) {
                    const int sid = sh_sid;
                    float pos  = 0.0f;
                    float minv = 1e30f;   // strict < == argmin first-index tie rule
                    float neg  = 0.0f;
                    #pragma unroll
                    for (int s = 0; s < SS; ++s) {
                        float ds = sqrtf(__shfl_sync(0xffffffffu, tot, s));
                        if (s == sid) pos = ds;
                        bool valid = (sh_mask[s] != 0) && (s != sid);
                        float m = valid ? ds : 10.0f;          // SENTINEL
                        if (m < minv) { minv = m; neg = ds; }  // carry REAL dist at argmin
                    }
                    g_margin_part[b] = fmaxf(pos - neg + 0.5f, 0.0f);
                } else {
                    // non-zero lanes must still participate in the shfls above
                    #pragma unroll
                    for (int s = 0; s < SS; ++s)
                        (void)__shfl_sync(0xffffffffu, tot, s);
                }
            }
            __syncthreads();   // sh_red/sh_mask reusable next ticket
        } else {
            // ---- alpha chunk (256 threads) ----
            const int c     = (int)(t - NB);
            const int start = c * ALPHA_CHUNK;
            const int end   = min(start + ALPHA_CHUNK, ALPHA_ROWS);
            float part = 0.0f;
            for (int r = start + tid; r < end; r += THREADS) {
                const float* __restrict__ row = alpha + (size_t)r * 10;
                float s0 = 0.0f, mx = -1e30f;
                #pragma unroll
                for (int k = 0; k < 10; ++k) {
                    float v = row[k];
                    s0 += v;
                    mx = fmaxf(mx, v);
                }
                // row_sum==0 -> tmp=ones -> max=1 -> |1-1| = 0
                part += (s0 == 0.0f) ? 0.0f : fabsf(mx - 1.0f);
            }
            sh_blk[tid] = part;
            __syncthreads();
            #pragma unroll
            for (int off = THREADS / 2; off > 0; off >>= 1) {
                if (tid < off) sh_blk[tid] += sh_blk[tid + off];
                __syncthreads();
            }
            if (tid == 0) g_alpha_part[c] = sh_blk[0];
            __syncthreads();
        }
    }

    // ---- completion-counter fused finalize (last block only) ----
    __shared__ bool s_last;
    if (tid == 0) {
        __threadfence();
        unsigned int d = atomicAdd(&g_done, 1u);
        s_last = (d == (unsigned int)(gridDim.x - 1));
    }
    __syncthreads();
    if (!s_last) return;

    // margin sum, fixed order -> bit-deterministic
    float m = 0.0f;
    for (int i = tid; i < NB; i += THREADS) m += g_margin_part[i];
    sh_blk[tid] = m;
    __syncthreads();
    #pragma unroll
    for (int off = THREADS / 2; off > 0; off >>= 1) {
        if (tid < off) sh_blk[tid] += sh_blk[tid + off];
        __syncthreads();
    }
    float margin = sh_blk[0];
    __syncthreads();

    // alpha sum
    sh_blk[tid] = (tid < ALPHA_CHUNKS) ? g_alpha_part[tid] : 0.0f;
    __syncthreads();
    #pragma unroll
    for (int off = THREADS / 2; off > 0; off >>= 1) {
        if (tid < off) sh_blk[tid] += sh_blk[tid + off];
        __syncthreads();
    }
    float alpha_term = sh_blk[0];

    if (tid == 0) {
        float loss = margin * 0.875f + alpha_term * 0.125f;
        out[0] = loss;
        if (out_size > 1) out[1] = margin;
        if (out_size > 2) out[2] = alpha_term;
        // self-reset for next graph replay (stream order guarantees visibility)
        g_ticket = 0u;
        g_done   = 0u;
    }
}

extern "C" void kernel_launch(void* const* d_in, const int* in_sizes, int n_in,
                              void* d_out, int out_size)
{
    // Identify inputs robustly by element count (all distinct):
    //   sentence  8192*1024    = 8388608  (f32)
    //   all_gloss 8192*10*1024 = 83886080 (f32)
    //   alpha     2700*6*10    = 162000   (f32)
    //   sense_mask 8192*10     = 81920    (i32)
    //   sense_ids 8192         = 8192     (i32)
    const float* sentence = nullptr;
    const float* gloss    = nullptr;
    const float* alpha    = nullptr;
    const int*   mask     = nullptr;
    const int*   sids     = nullptr;
    for (int i = 0; i < n_in; ++i) {
        switch (in_sizes[i]) {
            case 8388608:  sentence = (const float*)d_in[i]; break;
            case 83886080: gloss    = (const float*)d_in[i]; break;
            case 162000:   alpha    = (const float*)d_in[i]; break;
            case 81920:    mask     = (const int*)  d_in[i]; break;
            case 8192:     sids     = (const int*)  d_in[i]; break;
            default: break;
        }
    }

    marginal_loss_fused<<<NBLOCKS, THREADS>>>(sentence, gloss, alpha, mask, sids,
                                              (float*)d_out, out_size);
}

// round 7
// speedup vs baseline: 1.6269x; 1.3749x over previous
#include <cuda_runtime.h>
#include <math.h>

// Problem shapes (fixed by the reference)
#define NB 8192          // batch
#define SS 10            // senses
#define HH 1024          // hidden
#define THREADS 256
#define NBLOCKS 740      // 5 blocks/SM x 148 SMs (48 regs -> natural 5-block residency)
#define ALPHA_ROWS 16200 // 2700*6
#define ALPHA_CHUNKS 64
#define ALPHA_CHUNK 254  // 64*254 = 16256 >= 16200
#define NTICKETS (NB + ALPHA_CHUNKS)

// Scratch (device globals: no allocation allowed anywhere)
__device__ float g_margin_part[NB];
__device__ float g_alpha_part[ALPHA_CHUNKS];
__device__ unsigned int g_ticket;  // zero-init; self-resetting
__device__ unsigned int g_done;    // zero-init; self-resetting

__global__ __launch_bounds__(THREADS)
void marginal_loss_fused(const float* __restrict__ sentence,
                         const float* __restrict__ gloss,
                         const float* __restrict__ alpha,
                         const int*   __restrict__ mask,
                         const int*   __restrict__ sids,
                         float* __restrict__ out, int out_size)
{
    const int lane = threadIdx.x & 31;

    // ---- dynamic ticket loop: perfect balance across SMs ----
    for (;;) {
        unsigned int t;
        if (lane == 0) t = atomicAdd(&g_ticket, 1u);
        t = __shfl_sync(0xffffffffu, t, 0);
        if (t >= NTICKETS) break;

        if (t < NB) {
            // ---- margin row t: one warp computes 10 distances in one pass ----
            const int b = (int)t;
            const float4* __restrict__ srow =
                reinterpret_cast<const float4*>(sentence + (size_t)b * HH);
            float4 sv[8];
            #pragma unroll
            for (int j = 0; j < 8; ++j) sv[j] = srow[lane + j * 32];

            float acc[SS];
            #pragma unroll
            for (int s = 0; s < SS; ++s) {
                const float4* __restrict__ grow = reinterpret_cast<const float4*>(
                    gloss + ((size_t)b * SS + s) * HH);
                float sum = 0.0f;   // single chain: exact R2 codegen (48 regs, no spill)
                #pragma unroll
                for (int j = 0; j < 8; ++j) {
                    float4 g = grow[lane + j * 32];
                    float d0 = sv[j].x - g.x + 1e-6f;
                    float d1 = sv[j].y - g.y + 1e-6f;
                    float d2 = sv[j].z - g.z + 1e-6f;
                    float d3 = sv[j].w - g.w + 1e-6f;
                    sum = fmaf(d0, d0, sum);
                    sum = fmaf(d1, d1, sum);
                    sum = fmaf(d2, d2, sum);
                    sum = fmaf(d3, d3, sum);
                }
                acc[s] = sum;
            }

            #pragma unroll
            for (int s = 0; s < SS; ++s) {
                float v = acc[s];
                #pragma unroll
                for (int off = 16; off > 0; off >>= 1)
                    v += __shfl_xor_sync(0xffffffffu, v, off);
                acc[s] = v;
            }

            if (lane == 0) {
                const int sid = sids[b];
                float pos  = 0.0f;
                float minv = 1e30f;   // first strict-< win == argmin first-index tie rule
                float neg  = 0.0f;
                #pragma unroll
                for (int s = 0; s < SS; ++s) {
                    float ds = sqrtf(acc[s]);
                    if (s == sid) pos = ds;
                    bool valid = (mask[b * SS + s] != 0) && (s != sid);
                    float m = valid ? ds : 10.0f;          // SENTINEL
                    if (m < minv) { minv = m; neg = ds; }  // carry REAL distance at argmin
                }
                g_margin_part[b] = fmaxf(pos - neg + 0.5f, 0.0f);
            }
        } else {
            // ---- alpha chunk ----
            const int c     = (int)(t - NB);
            const int start = c * ALPHA_CHUNK;
            const int end   = min(start + ALPHA_CHUNK, ALPHA_ROWS);
            float part = 0.0f;
            for (int r = start + lane; r < end; r += 32) {
                const float* __restrict__ row = alpha + (size_t)r * 10;
                float s0 = 0.0f, mx = -1e30f;
                #pragma unroll
                for (int k = 0; k < 10; ++k) {
                    float v = row[k];
                    s0 += v;
                    mx = fmaxf(mx, v);
                }
                // row_sum==0 -> tmp=ones -> max=1 -> |1-1| = 0
                part += (s0 == 0.0f) ? 0.0f : fabsf(mx - 1.0f);
            }
            #pragma unroll
            for (int off = 16; off > 0; off >>= 1)
                part += __shfl_xor_sync(0xffffffffu, part, off);
            if (lane == 0) g_alpha_part[c] = part;
        }
    }

    // ---- completion-counter fused finalize (last block only) ----
    __shared__ bool s_last;
    __syncthreads();
    if (threadIdx.x == 0) {
        __threadfence();
        unsigned int d = atomicAdd(&g_done, 1u);
        s_last = (d == (unsigned int)(gridDim.x - 1));
    }
    __syncthreads();
    if (!s_last) return;

    __shared__ float sh[THREADS];

    // margin sum, fixed order -> bit-deterministic
    float m = 0.0f;
    for (int i = threadIdx.x; i < NB; i += THREADS) m += g_margin_part[i];
    sh[threadIdx.x] = m;
    __syncthreads();
    #pragma unroll
    for (int off = THREADS / 2; off > 0; off >>= 1) {
        if (threadIdx.x < off) sh[threadIdx.x] += sh[threadIdx.x + off];
        __syncthreads();
    }
    float margin = sh[0];
    __syncthreads();

    // alpha sum
    float a = (threadIdx.x < ALPHA_CHUNKS) ? g_alpha_part[threadIdx.x] : 0.0f;
    sh[threadIdx.x] = a;
    __syncthreads();
    #pragma unroll
    for (int off = THREADS / 2; off > 0; off >>= 1) {
        if (threadIdx.x < off) sh[threadIdx.x] += sh[threadIdx.x + off];
        __syncthreads();
    }
    float alpha_term = sh[0];

    if (threadIdx.x == 0) {
        float loss = margin * 0.875f + alpha_term * 0.125f;
        out[0] = loss;
        if (out_size > 1) out[1] = margin;
        if (out_size > 2) out[2] = alpha_term;
        // self-reset for next graph replay (stream order guarantees visibility)
        g_ticket = 0u;
        g_done   = 0u;
    }
}

extern "C" void kernel_launch(void* const* d_in, const int* in_sizes, int n_in,
                              void* d_out, int out_size)
{
    // Identify inputs robustly by element count (all distinct):
    //   sentence  8192*1024    = 8388608  (f32)
    //   all_gloss 8192*10*1024 = 83886080 (f32)
    //   alpha     2700*6*10    = 162000   (f32)
    //   sense_mask 8192*10     = 81920    (i32)
    //   sense_ids 8192         = 8192     (i32)
    const float* sentence = nullptr;
    const float* gloss    = nullptr;
    const float* alpha    = nullptr;
    const int*   mask     = nullptr;
    const int*   sids     = nullptr;
    for (int i = 0; i < n_in; ++i) {
        switch (in_sizes[i]) {
            case 8388608:  sentence = (const float*)d_in[i]; break;
            case 83886080: gloss    = (const float*)d_in[i]; break;
            case 162000:   alpha    = (const float*)d_in[i]; break;
            case 81920:    mask     = (const int*)  d_in[i]; break;
            case 8192:     sids     = (const int*)  d_in[i]; break;
            default: break;
        }
    }

    marginal_loss_fused<<<NBLOCKS, THREADS>>>(sentence, gloss, alpha, mask, sids,
                                              (float*)d_out, out_size);
}